// round 9
// baseline (speedup 1.0000x reference)
#include <cuda_runtime.h>
#include <math.h>

#define NH   256     // B*H heads
#define SLEN 4096
#define DIM  128
#define RSEL 16
#define KSEL 256

// ---- device scratch (no allocations allowed) ----
__device__ float g_sc[NH * SLEN];     // approx scores
__device__ float g_lg[NH * SLEN];     // exact logits
__device__ float g_w[NH * SLEN];      // dense softmax weights (0 for unselected)
__device__ float g_vmean[NH * DIM];   // un-normalized V column sums
__device__ float g_y[NH * DIM];       // weighted V sums
__device__ float g_alpha[NH];
__device__ int   g_cntV[NH];

__device__ __forceinline__ unsigned fkey(float f) {
    unsigned u = __float_as_uint(f);
    return (u & 0x80000000u) ? ~u : (u | 0x80000000u);  // order-preserving float->uint
}

// ============================================================
// K1: score kernel. grid NH*8 (512 rows/CTA), block 256.
// 4 lanes per K row -> 8 rows per warp-instruction, so the dot
// reduction is 2 shuffle steps (x2 dots) per 8 rows instead of
// 5 steps per row. Loads stay fully coalesced (16 sectors/instr).
// ============================================================
__global__ __launch_bounds__(256, 5) void score_kernel(
    const float* __restrict__ Qg, const float* __restrict__ Kg)
{
    __shared__ float4 s_qm4[32];
    __shared__ float4 s_qf4[32];
    __shared__ float s_rs;

    int bid = blockIdx.x;
    int h = bid >> 3, c = bid & 7;
    int t = threadIdx.x, w = t >> 5, lane = t & 31;

    // ---------------- prep (warp 0 only) ----------------
    if (w == 0) {
        float4 qf = ((const float4*)(Qg + h * DIM))[lane];
        float a0 = fabsf(qf.x), a1 = fabsf(qf.y), a2 = fabsf(qf.z), a3 = fabsf(qf.w);
        float sumall = a0 + a1 + a2 + a3;
#pragma unroll
        for (int off = 16; off; off >>= 1) sumall += __shfl_xor_sync(0xffffffffu, sumall, off);

        float r0 = a0, r1 = a1, r2 = a2, r3 = a3;
        unsigned selm = 0;
        float sumtop = 0.f;
#pragma unroll
        for (int it = 0; it < RSEL; it++) {
            float bv = r0; int bs = 0;
            if (r1 > bv) { bv = r1; bs = 1; }
            if (r2 > bv) { bv = r2; bs = 2; }
            if (r3 > bv) { bv = r3; bs = 3; }
            float v = bv; int ix = lane * 4 + bs;
#pragma unroll
            for (int off = 16; off; off >>= 1) {
                float ov = __shfl_xor_sync(0xffffffffu, v, off);
                int   oi = __shfl_xor_sync(0xffffffffu, ix, off);
                if (ov > v || (ov == v && oi < ix)) { v = ov; ix = oi; }
            }
            sumtop += v;
            if ((ix >> 2) == lane) {
                int s = ix & 3;
                if (s == 0) r0 = -1.f; else if (s == 1) r1 = -1.f;
                else if (s == 2) r2 = -1.f; else r3 = -1.f;
                selm |= 1u << s;
            }
        }
        float4 qm;
        qm.x = (selm & 1u) ? qf.x : 0.f;
        qm.y = (selm & 2u) ? qf.y : 0.f;
        qm.z = (selm & 4u) ? qf.z : 0.f;
        qm.w = (selm & 8u) ? qf.w : 0.f;
        s_qm4[lane] = qm;
        s_qf4[lane] = qf;
        if (lane == 0) s_rs = rsqrtf((float)DIM * sumtop / sumall);
    }
    __syncthreads();

    float rs = s_rs;
    const float invsq = 0.08838834764831845f;   // 1/sqrt(128)
    const float4* Kr = (const float4*)(Kg + (size_t)h * SLEN * DIM);
    int sub = lane >> 2;      // row-within-group 0..7
    int cl  = lane & 3;       // column lane 0..3
    int rowBase = c * 512 + w * 64;
    float* scp = g_sc + h * SLEN;
    float* lgp = g_lg + h * SLEN;

    for (int it = 0; it < 8; it++) {            // 8 rows per iter per warp
        int r = rowBase + it * 8 + sub;
        const float4* rowp = Kr + (size_t)r * 32 + cl;
        float dm = 0.f, df = 0.f;
        float4 kv[4];
        // cols 0..63 (4 chunks in flight)
#pragma unroll
        for (int j = 0; j < 4; j++) kv[j] = rowp[4 * j];
#pragma unroll
        for (int j = 0; j < 4; j++) {
            float4 qm = s_qm4[cl + 4 * j];
            float4 qf = s_qf4[cl + 4 * j];
            dm += qm.x * kv[j].x + qm.y * kv[j].y + qm.z * kv[j].z + qm.w * kv[j].w;
            df += qf.x * kv[j].x + qf.y * kv[j].y + qf.z * kv[j].z + qf.w * kv[j].w;
        }
        // cols 64..127
#pragma unroll
        for (int j = 0; j < 4; j++) kv[j] = rowp[16 + 4 * j];
#pragma unroll
        for (int j = 0; j < 4; j++) {
            float4 qm = s_qm4[16 + cl + 4 * j];
            float4 qf = s_qf4[16 + cl + 4 * j];
            dm += qm.x * kv[j].x + qm.y * kv[j].y + qm.z * kv[j].z + qm.w * kv[j].w;
            df += qf.x * kv[j].x + qf.y * kv[j].y + qf.z * kv[j].z + qf.w * kv[j].w;
        }
        // reduce across the 4 column lanes only
        dm += __shfl_xor_sync(0xffffffffu, dm, 1);
        dm += __shfl_xor_sync(0xffffffffu, dm, 2);
        df += __shfl_xor_sync(0xffffffffu, df, 1);
        df += __shfl_xor_sync(0xffffffffu, df, 2);
        if (cl == 0) {
            scp[r] = dm * rs;
            lgp[r] = df * invsq;
        }
    }
}

// ============================================================
// K2: select kernel. grid NH, block 256. Reads L2-resident
// g_sc/g_lg. Radix top-256, alpha, exact softmax, dense-weight
// scatter. Also zeroes vpass accumulators + counter.
// ============================================================
__global__ __launch_bounds__(256) void select_kernel()
{
    __shared__ float sc[SLEN];     // 16KB
    __shared__ float red[256];
    __shared__ int   hist[256];
    __shared__ int   scn[256];
    __shared__ int   idxs[KSEL];
    __shared__ int s_cntA, s_cntB;
    __shared__ float s_mx, s_Z, s_m2, s_Z2;
    __shared__ unsigned s_prefix;
    __shared__ int s_need;

    int h = blockIdx.x, t = threadIdx.x;

    // zero vpass accumulators + counter (stream-ordered before vpass)
    if (t < 32) {
        float4 zer = make_float4(0.f, 0.f, 0.f, 0.f);
        ((float4*)(g_vmean + h * DIM))[t] = zer;
        ((float4*)(g_y + h * DIM))[t] = zer;
    }
    if (t == 0) g_cntV[h] = 0;

    for (int i = t; i < SLEN; i += 256) sc[i] = g_sc[h * SLEN + i];
    __syncthreads();

    // max
    float mx = -3.4e38f;
    for (int i = t; i < SLEN; i += 256) mx = fmaxf(mx, sc[i]);
    red[t] = mx; __syncthreads();
    for (int s = 128; s > 0; s >>= 1) { if (t < s) red[t] = fmaxf(red[t], red[t + s]); __syncthreads(); }
    if (t == 0) s_mx = red[0];
    __syncthreads();
    mx = s_mx;

    // Z
    float z = 0.f;
    for (int i = t; i < SLEN; i += 256) z += __expf(sc[i] - mx);
    red[t] = z; __syncthreads();
    for (int s = 128; s > 0; s >>= 1) { if (t < s) red[t] += red[t + s]; __syncthreads(); }
    if (t == 0) s_Z = red[0];
    __syncthreads();

    // radix top-KSEL threshold
    unsigned prefix = 0; int need = KSEL;
    for (int pass = 0; pass < 4; pass++) {
        int shift = 24 - 8 * pass;
        hist[t] = 0;
        __syncthreads();
        for (int i = t; i < SLEN; i += 256) {
            unsigned u = fkey(sc[i]);
            unsigned hb = (pass == 0) ? 0u : (u >> (shift + 8));
            unsigned pb = (pass == 0) ? 0u : (prefix >> (shift + 8));
            if (hb == pb) atomicAdd(&hist[(u >> shift) & 255], 1);
        }
        __syncthreads();
        scn[t] = hist[t];
        __syncthreads();
        for (int off = 1; off < 256; off <<= 1) {   // inclusive suffix sum
            int v = scn[t] + ((t + off < 256) ? scn[t + off] : 0);
            __syncthreads();
            scn[t] = v;
            __syncthreads();
        }
        {
            int above = (t + 1 < 256) ? scn[t + 1] : 0;
            if (above < need && above + hist[t] >= need) {
                s_prefix = prefix | ((unsigned)t << shift);
                s_need = need - above;
            }
        }
        __syncthreads();
        prefix = s_prefix; need = s_need;
        __syncthreads();
    }
    unsigned T = prefix;
    int nEq = s_need, nAbove = KSEL - nEq;

    // compaction: >T into [0,nAbove), ==T into [nAbove,KSEL)
    if (t == 0) { s_cntA = 0; s_cntB = 0; }
    __syncthreads();
    for (int i = t; i < SLEN; i += 256) {
        unsigned u = fkey(sc[i]);
        if (u > T) { int p = atomicAdd(&s_cntA, 1); idxs[p] = i; }
        else if (u == T) { int p = atomicAdd(&s_cntB, 1); if (p < nEq) idxs[nAbove + p] = i; }
    }
    __syncthreads();

    // alpha = sum of top-k approx softmax probs
    float an = __expf(sc[idxs[t]] - mx);
    red[t] = an; __syncthreads();
    for (int s = 128; s > 0; s >>= 1) { if (t < s) red[t] += red[t + s]; __syncthreads(); }
    if (t == 0) g_alpha[h] = red[0] / s_Z;
    __syncthreads();

    // exact softmax over selected rows — logits precomputed (L2 hit)
    float l = g_lg[h * SLEN + idxs[t]];
    red[t] = l; __syncthreads();
    for (int s = 128; s > 0; s >>= 1) { if (t < s) red[t] = fmaxf(red[t], red[t + s]); __syncthreads(); }
    if (t == 0) s_m2 = red[0];
    __syncthreads();
    float e = __expf(l - s_m2);
    red[t] = e; __syncthreads();
    for (int s = 128; s > 0; s >>= 1) { if (t < s) red[t] += red[t + s]; __syncthreads(); }
    if (t == 0) s_Z2 = red[0];
    __syncthreads();

    // zero dense weight row, then scatter selected weights
    for (int i = t; i < SLEN; i += 256) g_w[h * SLEN + i] = 0.f;
    __syncthreads();
    g_w[h * SLEN + idxs[t]] = e / s_Z2;
}

// ============================================================
// K3: single pass over V (proven 83-87% DRAM). Accumulates V_mean
// and weighted sums; last CTA per head combines + writes output.
// grid NH*8, block 256
// ============================================================
__global__ __launch_bounds__(256) void vpass_kernel(const float* __restrict__ Vg,
                                                    float* __restrict__ out) {
    int bid = blockIdx.x; int h = bid >> 3; int chunk = bid & 7;
    int t = threadIdx.x; int g = t >> 5; int lane = t & 31;
    const float4* Vr = (const float4*)(Vg + (size_t)h * SLEN * DIM);
    const float* wrow = g_w + h * SLEN + chunk * 512;
    int base = chunk * 512;
    float4 am = make_float4(0.f, 0.f, 0.f, 0.f);
    float4 ay = make_float4(0.f, 0.f, 0.f, 0.f);

    for (int it = 0; it < 64; it += 8) {   // warp g owns rows g + 8*m; 8 rows in flight
        float4 v[8]; float wv[8];
#pragma unroll
        for (int j = 0; j < 8; j++) {
            int r = g + 8 * (it + j);
            v[j] = Vr[(size_t)(base + r) * 32 + lane];
            wv[j] = wrow[r];                 // uniform broadcast load
        }
#pragma unroll
        for (int j = 0; j < 8; j++) {
            am.x += v[j].x; am.y += v[j].y; am.z += v[j].z; am.w += v[j].w;
            ay.x += wv[j] * v[j].x; ay.y += wv[j] * v[j].y;
            ay.z += wv[j] * v[j].z; ay.w += wv[j] * v[j].w;
        }
    }
    __shared__ float4 bm[8][32];
    __shared__ float4 by[8][32];
    __shared__ int s_last;
    bm[g][lane] = am; by[g][lane] = ay;
    __syncthreads();
    if (t < 32) {
        float4 smv = bm[0][t], syv = by[0][t];
#pragma unroll
        for (int i = 1; i < 8; i++) {
            float4 a = bm[i][t], b = by[i][t];
            smv.x += a.x; smv.y += a.y; smv.z += a.z; smv.w += a.w;
            syv.x += b.x; syv.y += b.y; syv.z += b.z; syv.w += b.w;
        }
        float* dm = g_vmean + h * DIM + t * 4;
        float* dy = g_y + h * DIM + t * 4;
        atomicAdd(dm + 0, smv.x); atomicAdd(dm + 1, smv.y);
        atomicAdd(dm + 2, smv.z); atomicAdd(dm + 3, smv.w);
        atomicAdd(dy + 0, syv.x); atomicAdd(dy + 1, syv.y);
        atomicAdd(dy + 2, syv.z); atomicAdd(dy + 3, syv.w);
    }
    __syncthreads();
    if (t == 0) {
        __threadfence();                         // publish this CTA's accumulations
        s_last = (atomicAdd(&g_cntV[h], 1) == 7);
        if (s_last) __threadfence();
    }
    __syncthreads();
    if (s_last && t < 32) {                      // last CTA for this head combines
        const float inv = 1.f / (float)SLEN;
        float alpha = g_alpha[h];
        float4 vm = ((const float4*)(g_vmean + h * DIM))[t];
        float4 y  = ((const float4*)(g_y + h * DIM))[t];
        vm.x *= inv; vm.y *= inv; vm.z *= inv; vm.w *= inv;
        float4 o;
        o.x = vm.x + alpha * (y.x - vm.x);
        o.y = vm.y + alpha * (y.y - vm.y);
        o.z = vm.z + alpha * (y.z - vm.z);
        o.w = vm.w + alpha * (y.w - vm.w);
        ((float4*)out)[h * 32 + t] = o;
    }
}

extern "C" void kernel_launch(void* const* d_in, const int* in_sizes, int n_in,
                              void* d_out, int out_size) {
    const float* Q = (const float*)d_in[0];
    const float* K = (const float*)d_in[1];
    const float* V = (const float*)d_in[2];
    // d_in[3] = mask (all true), d_in[4]=r, d_in[5]=k (compile-time constants)
    float* out = (float*)d_out;

    score_kernel<<<NH * 8, 256>>>(Q, K);
    select_kernel<<<NH, 256>>>();
    vpass_kernel<<<NH * 8, 256>>>(V, out);
}

// round 11
// speedup vs baseline: 1.4668x; 1.4668x over previous
#include <cuda_runtime.h>
#include <math.h>

#define NH   256     // B*H heads
#define SLEN 4096
#define DIM  128
#define RSEL 16
#define KSEL 256

// ---- device scratch (no atomics/counters -> graph-replay safe) ----
__device__ float g_sc[NH * SLEN];         // approx scores
__device__ float g_vpart[NH * 8 * DIM];   // per-CTA partial V column sums

__device__ __forceinline__ unsigned fkey(float f) {
    unsigned u = __float_as_uint(f);
    return (u & 0x80000000u) ? ~u : (u | 0x80000000u);  // order-preserving float->uint
}

// ============================================================
// K1: stream kernel. grid NH*8, block 256 (8 warps).
//  - warp 0 prep: top-16 |Q| dims + scale -> smem (masked q only)
//  - K loop: 512 rows, masked dot (R1-proven shape: q in regs,
//    MLP=4, 32-lane shuffle reduce) -> g_sc
//  - V loop: 512 rows, plain column sums (vpass-proven shape)
//    -> g_vpart[bid] (no atomics)
// ============================================================
__global__ __launch_bounds__(256, 7) void stream_kernel(
    const float* __restrict__ Qg, const float* __restrict__ Kg,
    const float* __restrict__ Vg)
{
    __shared__ float4 s_qm4[32];
    __shared__ float s_rs;
    __shared__ float4 bm[8][32];

    int bid = blockIdx.x;
    int h = bid >> 3, c = bid & 7;
    int t = threadIdx.x, w = t >> 5, lane = t & 31;

    // ---------------- prep (warp 0 only) ----------------
    if (w == 0) {
        float4 qf = ((const float4*)(Qg + h * DIM))[lane];
        float a0 = fabsf(qf.x), a1 = fabsf(qf.y), a2 = fabsf(qf.z), a3 = fabsf(qf.w);
        float sumall = a0 + a1 + a2 + a3;
#pragma unroll
        for (int off = 16; off; off >>= 1) sumall += __shfl_xor_sync(0xffffffffu, sumall, off);

        float r0 = a0, r1 = a1, r2 = a2, r3 = a3;
        unsigned selm = 0;
        float sumtop = 0.f;
#pragma unroll
        for (int it = 0; it < RSEL; it++) {
            float bv = r0; int bs = 0;
            if (r1 > bv) { bv = r1; bs = 1; }
            if (r2 > bv) { bv = r2; bs = 2; }
            if (r3 > bv) { bv = r3; bs = 3; }
            float v = bv; int ix = lane * 4 + bs;
#pragma unroll
            for (int off = 16; off; off >>= 1) {
                float ov = __shfl_xor_sync(0xffffffffu, v, off);
                int   oi = __shfl_xor_sync(0xffffffffu, ix, off);
                if (ov > v || (ov == v && oi < ix)) { v = ov; ix = oi; }
            }
            sumtop += v;
            if ((ix >> 2) == lane) {
                int s = ix & 3;
                if (s == 0) r0 = -1.f; else if (s == 1) r1 = -1.f;
                else if (s == 2) r2 = -1.f; else r3 = -1.f;
                selm |= 1u << s;
            }
        }
        float4 qm;
        qm.x = (selm & 1u) ? qf.x : 0.f;
        qm.y = (selm & 2u) ? qf.y : 0.f;
        qm.z = (selm & 4u) ? qf.z : 0.f;
        qm.w = (selm & 8u) ? qf.w : 0.f;
        s_qm4[lane] = qm;
        if (lane == 0) s_rs = rsqrtf((float)DIM * sumtop / sumall);
    }
    __syncthreads();

    float4 qm = s_qm4[lane];          // q in registers for the whole K loop
    float rs = s_rs;
    int base = c * 512;

    // ---------------- K loop: masked dot over 512 rows ----------------
    {
        const float4* Kr = (const float4*)(Kg + (size_t)h * SLEN * DIM);
        float* scp = g_sc + h * SLEN + base;
        for (int it = 0; it < 64; it += 4) {          // warp w: rows w+8m, 4 in flight
            float4 kv[4];
#pragma unroll
            for (int j = 0; j < 4; j++)
                kv[j] = Kr[(size_t)(base + w + 8 * (it + j)) * 32 + lane];
            float d[4];
#pragma unroll
            for (int j = 0; j < 4; j++)
                d[j] = qm.x * kv[j].x + qm.y * kv[j].y + qm.z * kv[j].z + qm.w * kv[j].w;
#pragma unroll
            for (int off = 16; off; off >>= 1) {
#pragma unroll
                for (int j = 0; j < 4; j++)
                    d[j] += __shfl_xor_sync(0xffffffffu, d[j], off);
            }
            if (lane == 0) {
#pragma unroll
                for (int j = 0; j < 4; j++)
                    scp[w + 8 * (it + j)] = d[j] * rs;
            }
        }
    }

    // ---------------- V loop: plain column sums over 512 rows ----------------
    {
        const float4* Vr = (const float4*)(Vg + (size_t)h * SLEN * DIM);
        float4 am = make_float4(0.f, 0.f, 0.f, 0.f);
        for (int it = 0; it < 64; it += 8) {          // 8 rows in flight
            float4 v[8];
#pragma unroll
            for (int j = 0; j < 8; j++)
                v[j] = Vr[(size_t)(base + w + 8 * (it + j)) * 32 + lane];
#pragma unroll
            for (int j = 0; j < 8; j++) {
                am.x += v[j].x; am.y += v[j].y; am.z += v[j].z; am.w += v[j].w;
            }
        }
        bm[w][lane] = am;
        __syncthreads();
        if (t < 32) {
            float4 s = bm[0][t];
#pragma unroll
            for (int i = 1; i < 8; i++) {
                float4 a = bm[i][t];
                s.x += a.x; s.y += a.y; s.z += a.z; s.w += a.w;
            }
            ((float4*)(g_vpart + (size_t)bid * DIM))[t] = s;
        }
    }
}

// ============================================================
// K2: select kernel. grid NH, block 256.
//  radix top-256 on g_sc (L2), alpha, K-row gather -> exact
//  logits -> softmax, V-row gather -> y, reduce vpart -> V_mean,
//  combine, write out.
// ============================================================
__global__ __launch_bounds__(256) void select_kernel(
    const float* __restrict__ Qg, const float* __restrict__ Kg,
    const float* __restrict__ Vg, float* __restrict__ out)
{
    __shared__ float sc[SLEN];     // 16KB
    __shared__ float red[256];
    __shared__ int   hist[256];
    __shared__ int   scn[256];
    __shared__ int   idxs[KSEL];
    __shared__ float wts[KSEL];
    __shared__ float4 s_qf4[32];
    __shared__ float4 yb[8][32];   // 4KB
    __shared__ int s_cntA, s_cntB;
    __shared__ float s_mx, s_Z, s_m2, s_Z2, s_alpha;
    __shared__ unsigned s_prefix;
    __shared__ int s_need;

    int h = blockIdx.x, t = threadIdx.x;
    int w = t >> 5, lane = t & 31;

    if (t < 32) s_qf4[t] = ((const float4*)(Qg + h * DIM))[t];
    for (int i = t; i < SLEN; i += 256) sc[i] = g_sc[h * SLEN + i];
    __syncthreads();

    // ---- max over 4096 ----
    float mx = -3.4e38f;
    for (int i = t; i < SLEN; i += 256) mx = fmaxf(mx, sc[i]);
    red[t] = mx; __syncthreads();
    for (int s = 128; s > 0; s >>= 1) { if (t < s) red[t] = fmaxf(red[t], red[t + s]); __syncthreads(); }
    if (t == 0) s_mx = red[0];
    __syncthreads();
    mx = s_mx;

    // ---- Z = sum exp ----
    float z = 0.f;
    for (int i = t; i < SLEN; i += 256) z += __expf(sc[i] - mx);
    red[t] = z; __syncthreads();
    for (int s = 128; s > 0; s >>= 1) { if (t < s) red[t] += red[t + s]; __syncthreads(); }
    if (t == 0) s_Z = red[0];
    __syncthreads();

    // ---- exact radix top-KSEL threshold on fkey(score) ----
    unsigned prefix = 0; int need = KSEL;
    for (int pass = 0; pass < 4; pass++) {
        int shift = 24 - 8 * pass;
        hist[t] = 0;
        __syncthreads();
        for (int i = t; i < SLEN; i += 256) {
            unsigned u = fkey(sc[i]);
            unsigned hb = (pass == 0) ? 0u : (u >> (shift + 8));
            unsigned pb = (pass == 0) ? 0u : (prefix >> (shift + 8));
            if (hb == pb) atomicAdd(&hist[(u >> shift) & 255], 1);
        }
        __syncthreads();
        scn[t] = hist[t];
        __syncthreads();
        for (int off = 1; off < 256; off <<= 1) {    // inclusive suffix sum
            int v = scn[t] + ((t + off < 256) ? scn[t + off] : 0);
            __syncthreads();
            scn[t] = v;
            __syncthreads();
        }
        {
            int above = (t + 1 < 256) ? scn[t + 1] : 0;
            if (above < need && above + hist[t] >= need) {
                s_prefix = prefix | ((unsigned)t << shift);
                s_need = need - above;
            }
        }
        __syncthreads();
        prefix = s_prefix; need = s_need;
        __syncthreads();
    }
    unsigned T = prefix;
    int nEq = s_need, nAbove = KSEL - nEq;

    // ---- compaction: >T into [0,nAbove), ==T into [nAbove,KSEL) ----
    if (t == 0) { s_cntA = 0; s_cntB = 0; }
    __syncthreads();
    for (int i = t; i < SLEN; i += 256) {
        unsigned u = fkey(sc[i]);
        if (u > T) { int p = atomicAdd(&s_cntA, 1); idxs[p] = i; }
        else if (u == T) { int p = atomicAdd(&s_cntB, 1); if (p < nEq) idxs[nAbove + p] = i; }
    }
    __syncthreads();

    // ---- alpha = sum of top-k approx softmax probs ----
    float an = __expf(sc[idxs[t]] - mx);
    red[t] = an; __syncthreads();
    for (int s = 128; s > 0; s >>= 1) { if (t < s) red[t] += red[t + s]; __syncthreads(); }
    if (t == 0) s_alpha = red[0] / s_Z;
    __syncthreads();

    // ---- exact logits: gather 256 K rows (4 lanes/row, 8 chunks in flight) ----
    {
        const float invsq = 0.08838834764831845f;    // 1/sqrt(128)
        const float4* Kr = (const float4*)(Kg + (size_t)h * SLEN * DIM);
        int sub = lane >> 2, cl = lane & 3;
#pragma unroll 1
        for (int g8 = 0; g8 < 4; g8++) {             // 8 rows per iter per warp
            int j = w * 32 + g8 * 8 + sub;
            int row = idxs[j];
            const float4* rowp = Kr + (size_t)row * 32 + cl;
            float4 kv[8];
#pragma unroll
            for (int jj = 0; jj < 8; jj++) kv[jj] = rowp[4 * jj];
            float d = 0.f;
#pragma unroll
            for (int jj = 0; jj < 8; jj++) {
                float4 q = s_qf4[cl + 4 * jj];
                d += q.x * kv[jj].x + q.y * kv[jj].y + q.z * kv[jj].z + q.w * kv[jj].w;
            }
            d += __shfl_xor_sync(0xffffffffu, d, 1);
            d += __shfl_xor_sync(0xffffffffu, d, 2);
            if (cl == 0) wts[j] = d * invsq;
        }
    }
    __syncthreads();

    // ---- softmax over 256 exact logits ----
    float l = wts[t];
    red[t] = l; __syncthreads();
    for (int s = 128; s > 0; s >>= 1) { if (t < s) red[t] = fmaxf(red[t], red[t + s]); __syncthreads(); }
    if (t == 0) s_m2 = red[0];
    __syncthreads();
    float e = __expf(l - s_m2);
    red[t] = e; __syncthreads();
    for (int s = 128; s > 0; s >>= 1) { if (t < s) red[t] += red[t + s]; __syncthreads(); }
    if (t == 0) s_Z2 = red[0];
    __syncthreads();
    wts[t] = e / s_Z2;                    // final probabilities
    __syncthreads();

    // ---- y = sum_j w_j V[idx_j]: gather 256 V rows (warp-per-row, 4 in flight) ----
    {
        const float4* Vr = (const float4*)(Vg + (size_t)h * SLEN * DIM);
        float4 acc = make_float4(0.f, 0.f, 0.f, 0.f);
#pragma unroll 1
        for (int m = 0; m < 32; m += 4) {
            float4 v[4]; float wv[4];
#pragma unroll
            for (int jj = 0; jj < 4; jj++) {
                int j = w * 32 + m + jj;
                v[jj] = Vr[(size_t)idxs[j] * 32 + lane];
                wv[jj] = wts[j];
            }
#pragma unroll
            for (int jj = 0; jj < 4; jj++) {
                acc.x += wv[jj] * v[jj].x; acc.y += wv[jj] * v[jj].y;
                acc.z += wv[jj] * v[jj].z; acc.w += wv[jj] * v[jj].w;
            }
        }
        yb[w][lane] = acc;
    }
    __syncthreads();

    // ---- reduce y partials, reduce vpart -> V_mean, combine, write out ----
    if (t < 32) {
        float4 y = yb[0][t];
#pragma unroll
        for (int i = 1; i < 8; i++) {
            float4 a = yb[i][t];
            y.x += a.x; y.y += a.y; y.z += a.z; y.w += a.w;
        }
        float4 vm = make_float4(0.f, 0.f, 0.f, 0.f);
#pragma unroll
        for (int c = 0; c < 8; c++) {
            float4 p = ((const float4*)(g_vpart + (size_t)(h * 8 + c) * DIM))[t];
            vm.x += p.x; vm.y += p.y; vm.z += p.z; vm.w += p.w;
        }
        const float inv = 1.f / (float)SLEN;
        vm.x *= inv; vm.y *= inv; vm.z *= inv; vm.w *= inv;
        float alpha = s_alpha;
        float4 o;
        o.x = vm.x + alpha * (y.x - vm.x);
        o.y = vm.y + alpha * (y.y - vm.y);
        o.z = vm.z + alpha * (y.z - vm.z);
        o.w = vm.w + alpha * (y.w - vm.w);
        ((float4*)out)[h * 32 + t] = o;
    }
}

extern "C" void kernel_launch(void* const* d_in, const int* in_sizes, int n_in,
                              void* d_out, int out_size) {
    const float* Q = (const float*)d_in[0];
    const float* K = (const float*)d_in[1];
    const float* V = (const float*)d_in[2];
    // d_in[3] = mask (all true), d_in[4]=r, d_in[5]=k (compile-time constants)
    float* out = (float*)d_out;

    stream_kernel<<<NH * 8, 256>>>(Q, K, V);
    select_kernel<<<NH, 256>>>(Q, K, V, out);
}

// round 12
// speedup vs baseline: 1.5057x; 1.0265x over previous
#include <cuda_runtime.h>
#include <math.h>

#define NH   256     // B*H heads
#define SLEN 4096
#define DIM  128
#define RSEL 16
#define KSEL 256

// ---- device scratch (no atomics/counters -> graph-replay safe) ----
__device__ float g_sc[NH * SLEN];         // approx scores
__device__ float g_vpart[NH * 8 * DIM];   // per-CTA partial V column sums

__device__ __forceinline__ unsigned fkey(float f) {
    unsigned u = __float_as_uint(f);
    return (u & 0x80000000u) ? ~u : (u | 0x80000000u);  // order-preserving float->uint
}

// ============================================================
// K1: stream kernel (UNCHANGED — measured 6.4TB/s). grid NH*8,
// block 256. Masked-dot K loop + plain-sum V loop.
// ============================================================
__global__ __launch_bounds__(256, 7) void stream_kernel(
    const float* __restrict__ Qg, const float* __restrict__ Kg,
    const float* __restrict__ Vg)
{
    __shared__ float4 s_qm4[32];
    __shared__ float s_rs;
    __shared__ float4 bm[8][32];

    int bid = blockIdx.x;
    int h = bid >> 3, c = bid & 7;
    int t = threadIdx.x, w = t >> 5, lane = t & 31;

    if (w == 0) {
        float4 qf = ((const float4*)(Qg + h * DIM))[lane];
        float a0 = fabsf(qf.x), a1 = fabsf(qf.y), a2 = fabsf(qf.z), a3 = fabsf(qf.w);
        float sumall = a0 + a1 + a2 + a3;
#pragma unroll
        for (int off = 16; off; off >>= 1) sumall += __shfl_xor_sync(0xffffffffu, sumall, off);

        float r0 = a0, r1 = a1, r2 = a2, r3 = a3;
        unsigned selm = 0;
        float sumtop = 0.f;
#pragma unroll
        for (int it = 0; it < RSEL; it++) {
            float bv = r0; int bs = 0;
            if (r1 > bv) { bv = r1; bs = 1; }
            if (r2 > bv) { bv = r2; bs = 2; }
            if (r3 > bv) { bv = r3; bs = 3; }
            float v = bv; int ix = lane * 4 + bs;
#pragma unroll
            for (int off = 16; off; off >>= 1) {
                float ov = __shfl_xor_sync(0xffffffffu, v, off);
                int   oi = __shfl_xor_sync(0xffffffffu, ix, off);
                if (ov > v || (ov == v && oi < ix)) { v = ov; ix = oi; }
            }
            sumtop += v;
            if ((ix >> 2) == lane) {
                int s = ix & 3;
                if (s == 0) r0 = -1.f; else if (s == 1) r1 = -1.f;
                else if (s == 2) r2 = -1.f; else r3 = -1.f;
                selm |= 1u << s;
            }
        }
        float4 qm;
        qm.x = (selm & 1u) ? qf.x : 0.f;
        qm.y = (selm & 2u) ? qf.y : 0.f;
        qm.z = (selm & 4u) ? qf.z : 0.f;
        qm.w = (selm & 8u) ? qf.w : 0.f;
        s_qm4[lane] = qm;
        if (lane == 0) s_rs = rsqrtf((float)DIM * sumtop / sumall);
    }
    __syncthreads();

    float4 qm = s_qm4[lane];
    float rs = s_rs;
    int base = c * 512;

    {   // K loop
        const float4* Kr = (const float4*)(Kg + (size_t)h * SLEN * DIM);
        float* scp = g_sc + h * SLEN + base;
        for (int it = 0; it < 64; it += 4) {
            float4 kv[4];
#pragma unroll
            for (int j = 0; j < 4; j++)
                kv[j] = Kr[(size_t)(base + w + 8 * (it + j)) * 32 + lane];
            float d[4];
#pragma unroll
            for (int j = 0; j < 4; j++)
                d[j] = qm.x * kv[j].x + qm.y * kv[j].y + qm.z * kv[j].z + qm.w * kv[j].w;
#pragma unroll
            for (int off = 16; off; off >>= 1) {
#pragma unroll
                for (int j = 0; j < 4; j++)
                    d[j] += __shfl_xor_sync(0xffffffffu, d[j], off);
            }
            if (lane == 0) {
#pragma unroll
                for (int j = 0; j < 4; j++)
                    scp[w + 8 * (it + j)] = d[j] * rs;
            }
        }
    }

    {   // V loop
        const float4* Vr = (const float4*)(Vg + (size_t)h * SLEN * DIM);
        float4 am = make_float4(0.f, 0.f, 0.f, 0.f);
        for (int it = 0; it < 64; it += 8) {
            float4 v[8];
#pragma unroll
            for (int j = 0; j < 8; j++)
                v[j] = Vr[(size_t)(base + w + 8 * (it + j)) * 32 + lane];
#pragma unroll
            for (int j = 0; j < 8; j++) {
                am.x += v[j].x; am.y += v[j].y; am.z += v[j].z; am.w += v[j].w;
            }
        }
        bm[w][lane] = am;
        __syncthreads();
        if (t < 32) {
            float4 s = bm[0][t];
#pragma unroll
            for (int i = 1; i < 8; i++) {
                float4 a = bm[i][t];
                s.x += a.x; s.y += a.y; s.z += a.z; s.w += a.w;
            }
            ((float4*)(g_vpart + (size_t)bid * DIM))[t] = s;
        }
    }
}

// ============================================================
// K2: select kernel. grid NH, block 1024 (32 warps).
//  keys cached in registers; online softmax stats; shuffle-scan
//  radix; 32-warp K/V gathers. Combines + writes output.
// ============================================================
__global__ __launch_bounds__(1024, 1) void select_kernel(
    const float* __restrict__ Qg, const float* __restrict__ Kg,
    const float* __restrict__ Vg, float* __restrict__ out)
{
    __shared__ float sc[SLEN];       // 16KB
    __shared__ float4 yb[32][32];    // 16KB
    __shared__ int   hist[256];
    __shared__ int   idxs[KSEL];
    __shared__ float wts[KSEL];
    __shared__ float4 s_qf4[32];
    __shared__ float rmx[32], rsum[32];
    __shared__ int   warpsum[8], offs_s[8];
    __shared__ int s_cntA, s_cntB, s_need;
    __shared__ unsigned s_prefix;
    __shared__ float s_mx, s_Z, s_m2, s_Z2, s_alpha;

    int h = blockIdx.x, t = threadIdx.x;
    int w = t >> 5, lane = t & 31;

    if (t < 32) s_qf4[t] = ((const float4*)(Qg + h * DIM))[t];

    // ---- load scores: 1 float4 per thread; cache keys in registers ----
    float4 v4 = ((const float4*)(g_sc + h * SLEN))[t];
    sc[t * 4 + 0] = v4.x; sc[t * 4 + 1] = v4.y;
    sc[t * 4 + 2] = v4.z; sc[t * 4 + 3] = v4.w;
    unsigned k0 = fkey(v4.x), k1 = fkey(v4.y), k2 = fkey(v4.z), k3 = fkey(v4.w);

    // ---- online softmax stats (max + sumexp in ONE reduction) ----
    float lm = fmaxf(fmaxf(v4.x, v4.y), fmaxf(v4.z, v4.w));
    float ls = __expf(v4.x - lm) + __expf(v4.y - lm) + __expf(v4.z - lm) + __expf(v4.w - lm);
#pragma unroll
    for (int off = 16; off; off >>= 1) {
        float om = __shfl_xor_sync(0xffffffffu, lm, off);
        float os = __shfl_xor_sync(0xffffffffu, ls, off);
        float nm = fmaxf(lm, om);
        ls = ls * __expf(lm - nm) + os * __expf(om - nm);
        lm = nm;
    }
    if (lane == 0) { rmx[w] = lm; rsum[w] = ls; }
    __syncthreads();
    if (t < 32) {
        float m = rmx[t], s = ls = rsum[t];
#pragma unroll
        for (int off = 16; off; off >>= 1) {
            float om = __shfl_xor_sync(0xffffffffu, m, off);
            float os = __shfl_xor_sync(0xffffffffu, s, off);
            float nm = fmaxf(m, om);
            s = s * __expf(m - nm) + os * __expf(om - nm);
            m = nm;
        }
        if (t == 0) { s_mx = m; s_Z = s; }
    }
    __syncthreads();
    float mx = s_mx;

    // ---- radix top-KSEL threshold (keys in regs, shuffle-scan prefix) ----
    unsigned prefix = 0; int need = KSEL;
#pragma unroll 1
    for (int pass = 0; pass < 4; pass++) {
        int shift = 24 - 8 * pass;
        if (t < 256) hist[t] = 0;
        __syncthreads();
        unsigned pb = prefix >> (shift + 8);
        if (pass == 0 || (k0 >> (shift + 8)) == pb) atomicAdd(&hist[(k0 >> shift) & 255], 1);
        if (pass == 0 || (k1 >> (shift + 8)) == pb) atomicAdd(&hist[(k1 >> shift) & 255], 1);
        if (pass == 0 || (k2 >> (shift + 8)) == pb) atomicAdd(&hist[(k2 >> shift) & 255], 1);
        if (pass == 0 || (k3 >> (shift + 8)) == pb) atomicAdd(&hist[(k3 >> shift) & 255], 1);
        __syncthreads();
        // inclusive suffix sum over 256 bins: warp shuffle scan + 8 warp totals
        int sv = 0;
        if (t < 256) {
            sv = hist[t];
#pragma unroll
            for (int off = 1; off < 32; off <<= 1) {
                int n = __shfl_down_sync(0xffffffffu, sv, off);
                if (lane + off < 32) sv += n;
            }
            if (lane == 0) warpsum[w] = sv;   // w in 0..7 here
        }
        __syncthreads();
        if (t < 8) {
            int s = 0;
            for (int j = t + 1; j < 8; j++) s += warpsum[j];
            offs_s[t] = s;
        }
        __syncthreads();
        if (t < 256) {
            int scn = sv + offs_s[w];         // inclusive suffix (bins >= t)
            int above = scn - hist[t];        // strictly higher bins
            if (above < need && scn >= need) {
                s_prefix = prefix | ((unsigned)t << shift);
                s_need = need - above;
            }
        }
        __syncthreads();
        prefix = s_prefix; need = s_need;
        __syncthreads();
    }
    unsigned T = prefix;
    int nEq = need, nAbove = KSEL - nEq;

    // ---- compaction from registers: >T into [0,nAbove), ==T into [nAbove,KSEL) ----
    if (t == 0) { s_cntA = 0; s_cntB = 0; }
    __syncthreads();
    {
        int i0 = t * 4;
        if (k0 > T) idxs[atomicAdd(&s_cntA, 1)] = i0;
        else if (k0 == T) { int p = atomicAdd(&s_cntB, 1); if (p < nEq) idxs[nAbove + p] = i0; }
        if (k1 > T) idxs[atomicAdd(&s_cntA, 1)] = i0 + 1;
        else if (k1 == T) { int p = atomicAdd(&s_cntB, 1); if (p < nEq) idxs[nAbove + p] = i0 + 1; }
        if (k2 > T) idxs[atomicAdd(&s_cntA, 1)] = i0 + 2;
        else if (k2 == T) { int p = atomicAdd(&s_cntB, 1); if (p < nEq) idxs[nAbove + p] = i0 + 2; }
        if (k3 > T) idxs[atomicAdd(&s_cntA, 1)] = i0 + 3;
        else if (k3 == T) { int p = atomicAdd(&s_cntB, 1); if (p < nEq) idxs[nAbove + p] = i0 + 3; }
    }
    __syncthreads();

    // ---- alpha = sum of top-k approx softmax probs ----
    {
        float e = (t < KSEL) ? __expf(sc[idxs[t]] - mx) : 0.f;
#pragma unroll
        for (int off = 16; off; off >>= 1) e += __shfl_xor_sync(0xffffffffu, e, off);
        if (t < 256 && lane == 0) rsum[w] = e;     // w in 0..7
        __syncthreads();
        if (t == 0) {
            float s = 0.f;
            for (int j = 0; j < 8; j++) s += rsum[j];
            s_alpha = s / s_Z;
        }
    }
    __syncthreads();

    // ---- exact logits: 32 warps x 8 rows, warp-per-row, 4 in flight ----
    {
        const float invsq = 0.08838834764831845f;
        const float4* Kr = (const float4*)(Kg + (size_t)h * SLEN * DIM);
        float4 qv = s_qf4[lane];
#pragma unroll 1
        for (int m = 0; m < 8; m += 4) {
            float4 kv[4];
#pragma unroll
            for (int jj = 0; jj < 4; jj++)
                kv[jj] = Kr[(size_t)idxs[w * 8 + m + jj] * 32 + lane];
            float d[4];
#pragma unroll
            for (int jj = 0; jj < 4; jj++)
                d[jj] = qv.x * kv[jj].x + qv.y * kv[jj].y + qv.z * kv[jj].z + qv.w * kv[jj].w;
#pragma unroll
            for (int off = 16; off; off >>= 1) {
#pragma unroll
                for (int jj = 0; jj < 4; jj++)
                    d[jj] += __shfl_xor_sync(0xffffffffu, d[jj], off);
            }
            if (lane == 0) {
#pragma unroll
                for (int jj = 0; jj < 4; jj++)
                    wts[w * 8 + m + jj] = d[jj] * invsq;
            }
        }
    }
    __syncthreads();

    // ---- softmax over 256 exact logits (online, threads<256) ----
    {
        float l = (t < KSEL) ? wts[t] : -3.4e38f;
        float m = l, s = (t < KSEL) ? 1.f : 0.f;
#pragma unroll
        for (int off = 16; off; off >>= 1) {
            float om = __shfl_xor_sync(0xffffffffu, m, off);
            float os = __shfl_xor_sync(0xffffffffu, s, off);
            float nm = fmaxf(m, om);
            s = s * __expf(m - nm) + os * __expf(om - nm);
            m = nm;
        }
        if (t < 256 && lane == 0) { rmx[w] = m; rsum[w] = s; }
        __syncthreads();
        if (t == 0) {
            float M = rmx[0], S = rsum[0];
            for (int j = 1; j < 8; j++) {
                float nm = fmaxf(M, rmx[j]);
                S = S * __expf(M - nm) + rsum[j] * __expf(rmx[j] - nm);
                M = nm;
            }
            s_m2 = M; s_Z2 = S;
        }
        __syncthreads();
        if (t < KSEL) wts[t] = __expf(l - s_m2) / s_Z2;
    }
    __syncthreads();

    // ---- y: 32 warps x 8 V rows, 4 in flight ----
    {
        const float4* Vr = (const float4*)(Vg + (size_t)h * SLEN * DIM);
        float4 acc = make_float4(0.f, 0.f, 0.f, 0.f);
#pragma unroll 1
        for (int m = 0; m < 8; m += 4) {
            float4 vv[4]; float wv[4];
#pragma unroll
            for (int jj = 0; jj < 4; jj++) {
                int j = w * 8 + m + jj;
                vv[jj] = Vr[(size_t)idxs[j] * 32 + lane];
                wv[jj] = wts[j];
            }
#pragma unroll
            for (int jj = 0; jj < 4; jj++) {
                acc.x += wv[jj] * vv[jj].x; acc.y += wv[jj] * vv[jj].y;
                acc.z += wv[jj] * vv[jj].z; acc.w += wv[jj] * vv[jj].w;
            }
        }
        yb[w][lane] = acc;
    }
    __syncthreads();

    // ---- reduce y partials + vpart -> V_mean, combine, write out ----
    if (t < 32) {
        float4 y = yb[0][t];
#pragma unroll
        for (int i = 1; i < 32; i++) {
            float4 a = yb[i][t];
            y.x += a.x; y.y += a.y; y.z += a.z; y.w += a.w;
        }
        float4 vm = make_float4(0.f, 0.f, 0.f, 0.f);
#pragma unroll
        for (int c = 0; c < 8; c++) {
            float4 p = ((const float4*)(g_vpart + (size_t)(h * 8 + c) * DIM))[t];
            vm.x += p.x; vm.y += p.y; vm.z += p.z; vm.w += p.w;
        }
        const float inv = 1.f / (float)SLEN;
        vm.x *= inv; vm.y *= inv; vm.z *= inv; vm.w *= inv;
        float alpha = s_alpha;
        float4 o;
        o.x = vm.x + alpha * (y.x - vm.x);
        o.y = vm.y + alpha * (y.y - vm.y);
        o.z = vm.z + alpha * (y.z - vm.z);
        o.w = vm.w + alpha * (y.w - vm.w);
        ((float4*)out)[h * 32 + t] = o;
    }
}

extern "C" void kernel_launch(void* const* d_in, const int* in_sizes, int n_in,
                              void* d_out, int out_size) {
    const float* Q = (const float*)d_in[0];
    const float* K = (const float*)d_in[1];
    const float* V = (const float*)d_in[2];
    // d_in[3] = mask (all true), d_in[4]=r, d_in[5]=k (compile-time constants)
    float* out = (float*)d_out;

    stream_kernel<<<NH * 8, 256>>>(Q, K, V);
    select_kernel<<<NH, 1024>>>(Q, K, V, out);
}

// round 13
// speedup vs baseline: 1.5725x; 1.0444x over previous
#include <cuda_runtime.h>
#include <math.h>

#define NH   256     // B*H heads
#define SLEN 4096
#define DIM  128
#define RSEL 16
#define KSEL 256

// ---- device scratch (counters reset in-kernel -> graph-replay safe) ----
__device__ float g_sc[NH * SLEN];         // approx scores
__device__ float g_vpart[NH * 8 * DIM];   // per-CTA partial V column sums
__device__ float g_y[NH * DIM];           // attention output (pre-combine)
__device__ float g_alpha[NH];
__device__ int   g_done[NH];              // arrival counters (9 participants/head)

__device__ __forceinline__ unsigned fkey(float f) {
    unsigned u = __float_as_uint(f);
    return (u & 0x80000000u) ? ~u : (u | 0x80000000u);  // order-preserving float->uint
}

// ============================================================
// K1: kpass — K stream with masked dot (proven shape).
// grid NH*8, block 256.
// ============================================================
__global__ __launch_bounds__(256, 7) void kpass_kernel(
    const float* __restrict__ Qg, const float* __restrict__ Kg)
{
    __shared__ float4 s_qm4[32];
    __shared__ float s_rs;

    int bid = blockIdx.x;
    int h = bid >> 3, c = bid & 7;
    int t = threadIdx.x, w = t >> 5, lane = t & 31;

    // ---- prep (warp 0): top-16 |Q| dims + scale ----
    if (w == 0) {
        float4 qf = ((const float4*)(Qg + h * DIM))[lane];
        float a0 = fabsf(qf.x), a1 = fabsf(qf.y), a2 = fabsf(qf.z), a3 = fabsf(qf.w);
        float sumall = a0 + a1 + a2 + a3;
#pragma unroll
        for (int off = 16; off; off >>= 1) sumall += __shfl_xor_sync(0xffffffffu, sumall, off);

        float r0 = a0, r1 = a1, r2 = a2, r3 = a3;
        unsigned selm = 0;
        float sumtop = 0.f;
#pragma unroll
        for (int it = 0; it < RSEL; it++) {
            float bv = r0; int bs = 0;
            if (r1 > bv) { bv = r1; bs = 1; }
            if (r2 > bv) { bv = r2; bs = 2; }
            if (r3 > bv) { bv = r3; bs = 3; }
            float v = bv; int ix = lane * 4 + bs;
#pragma unroll
            for (int off = 16; off; off >>= 1) {
                float ov = __shfl_xor_sync(0xffffffffu, v, off);
                int   oi = __shfl_xor_sync(0xffffffffu, ix, off);
                if (ov > v || (ov == v && oi < ix)) { v = ov; ix = oi; }
            }
            sumtop += v;
            if ((ix >> 2) == lane) {
                int s = ix & 3;
                if (s == 0) r0 = -1.f; else if (s == 1) r1 = -1.f;
                else if (s == 2) r2 = -1.f; else r3 = -1.f;
                selm |= 1u << s;
            }
        }
        float4 qm;
        qm.x = (selm & 1u) ? qf.x : 0.f;
        qm.y = (selm & 2u) ? qf.y : 0.f;
        qm.z = (selm & 4u) ? qf.z : 0.f;
        qm.w = (selm & 8u) ? qf.w : 0.f;
        s_qm4[lane] = qm;
        if (lane == 0) s_rs = rsqrtf((float)DIM * sumtop / sumall);
    }
    __syncthreads();

    float4 qm = s_qm4[lane];
    float rs = s_rs;
    int base = c * 512;
    const float4* Kr = (const float4*)(Kg + (size_t)h * SLEN * DIM);
    float* scp = g_sc + h * SLEN + base;

    for (int it = 0; it < 64; it += 4) {           // warp w: rows w+8m, 4 in flight
        float4 kv[4];
#pragma unroll
        for (int j = 0; j < 4; j++)
            kv[j] = Kr[(size_t)(base + w + 8 * (it + j)) * 32 + lane];
        float d[4];
#pragma unroll
        for (int j = 0; j < 4; j++)
            d[j] = qm.x * kv[j].x + qm.y * kv[j].y + qm.z * kv[j].z + qm.w * kv[j].w;
#pragma unroll
        for (int off = 16; off; off >>= 1) {
#pragma unroll
            for (int j = 0; j < 4; j++)
                d[j] += __shfl_xor_sync(0xffffffffu, d[j], off);
        }
        if (lane == 0) {
#pragma unroll
            for (int j = 0; j < 4; j++)
                scp[w + 8 * (it + j)] = d[j] * rs;
        }
    }
}

// ============================================================
// K2: fused kernel. grid NH (select CTAs, first) + NH*8 (V-stream
// CTAs). block 256. Select work overlaps the V stream; the 9th
// (last) arriving CTA per head combines and writes the output.
// ============================================================
struct SelSm {
    float sc[SLEN];       // 16KB
    float red[256];
    int   hist[256];
    int   scn[256];
    int   idxs[KSEL];
    float wts[KSEL];
    float4 qf4[32];
    float4 yb[8][32];     // 4KB
};
struct VSm { float4 bm[8][32]; };
union FSm { SelSm s; VSm v; };

__global__ __launch_bounds__(256, 6) void fused_kernel(
    const float* __restrict__ Qg, const float* __restrict__ Kg,
    const float* __restrict__ Vg, float* __restrict__ out)
{
    __shared__ FSm sm;
    __shared__ float s_mx, s_Z, s_m2, s_Z2;
    __shared__ unsigned s_prefix;
    __shared__ int s_need, s_cntA, s_cntB, s_rank;

    int bid = blockIdx.x;
    int t = threadIdx.x, w = t >> 5, lane = t & 31;
    int h;

    if (bid < NH) {
        // ================== SELECT CTA (one per head) ==================
        h = bid;
        if (t < 32) sm.s.qf4[t] = ((const float4*)(Qg + h * DIM))[t];
        for (int i = t; i < SLEN; i += 256) sm.s.sc[i] = g_sc[h * SLEN + i];
        __syncthreads();

        // ---- online max+Z in one pass ----
        float lm = -3.4e38f, ls = 0.f;
        for (int i = t; i < SLEN; i += 256) {
            float v = sm.s.sc[i];
            float nm = fmaxf(lm, v);
            ls = ls * __expf(lm - nm) + __expf(v - nm);
            lm = nm;
        }
#pragma unroll
        for (int off = 16; off; off >>= 1) {
            float om = __shfl_xor_sync(0xffffffffu, lm, off);
            float os = __shfl_xor_sync(0xffffffffu, ls, off);
            float nm = fmaxf(lm, om);
            ls = ls * __expf(lm - nm) + os * __expf(om - nm);
            lm = nm;
        }
        if (lane == 0) { sm.s.red[w] = lm; sm.s.red[8 + w] = ls; }
        __syncthreads();
        if (t == 0) {
            float M = sm.s.red[0], S = sm.s.red[8];
            for (int j = 1; j < 8; j++) {
                float nm = fmaxf(M, sm.s.red[j]);
                S = S * __expf(M - nm) + sm.s.red[8 + j] * __expf(sm.s.red[j] - nm);
                M = nm;
            }
            s_mx = M; s_Z = S;
        }
        __syncthreads();
        float mx = s_mx;

        // ---- radix top-KSEL threshold ----
        unsigned prefix = 0; int need = KSEL;
        for (int pass = 0; pass < 4; pass++) {
            int shift = 24 - 8 * pass;
            sm.s.hist[t] = 0;
            __syncthreads();
            for (int i = t; i < SLEN; i += 256) {
                unsigned u = fkey(sm.s.sc[i]);
                unsigned hb = (pass == 0) ? 0u : (u >> (shift + 8));
                unsigned pb = (pass == 0) ? 0u : (prefix >> (shift + 8));
                if (hb == pb) atomicAdd(&sm.s.hist[(u >> shift) & 255], 1);
            }
            __syncthreads();
            sm.s.scn[t] = sm.s.hist[t];
            __syncthreads();
            for (int off = 1; off < 256; off <<= 1) {    // inclusive suffix sum
                int v = sm.s.scn[t] + ((t + off < 256) ? sm.s.scn[t + off] : 0);
                __syncthreads();
                sm.s.scn[t] = v;
                __syncthreads();
            }
            {
                int above = (t + 1 < 256) ? sm.s.scn[t + 1] : 0;
                if (above < need && above + sm.s.hist[t] >= need) {
                    s_prefix = prefix | ((unsigned)t << shift);
                    s_need = need - above;
                }
            }
            __syncthreads();
            prefix = s_prefix; need = s_need;
            __syncthreads();
        }
        unsigned T = prefix;
        int nEq = s_need, nAbove = KSEL - nEq;

        // ---- compaction ----
        if (t == 0) { s_cntA = 0; s_cntB = 0; }
        __syncthreads();
        for (int i = t; i < SLEN; i += 256) {
            unsigned u = fkey(sm.s.sc[i]);
            if (u > T) { int p = atomicAdd(&s_cntA, 1); sm.s.idxs[p] = i; }
            else if (u == T) { int p = atomicAdd(&s_cntB, 1); if (p < nEq) sm.s.idxs[nAbove + p] = i; }
        }
        __syncthreads();

        // ---- alpha ----
        float an = __expf(sm.s.sc[sm.s.idxs[t]] - mx);
        sm.s.red[t] = an; __syncthreads();
        for (int s = 128; s > 0; s >>= 1) { if (t < s) sm.s.red[t] += sm.s.red[t + s]; __syncthreads(); }
        if (t == 0) g_alpha[h] = sm.s.red[0] / s_Z;
        __syncthreads();

        // ---- exact logits: warp-per-row gather, 4 in flight ----
        {
            const float invsq = 0.08838834764831845f;
            const float4* Kr = (const float4*)(Kg + (size_t)h * SLEN * DIM);
            float4 qv = sm.s.qf4[lane];
#pragma unroll 1
            for (int m = 0; m < 32; m += 4) {
                float4 kv[4];
#pragma unroll
                for (int jj = 0; jj < 4; jj++)
                    kv[jj] = Kr[(size_t)sm.s.idxs[w * 32 + m + jj] * 32 + lane];
                float d[4];
#pragma unroll
                for (int jj = 0; jj < 4; jj++)
                    d[jj] = qv.x * kv[jj].x + qv.y * kv[jj].y + qv.z * kv[jj].z + qv.w * kv[jj].w;
#pragma unroll
                for (int off = 16; off; off >>= 1) {
#pragma unroll
                    for (int jj = 0; jj < 4; jj++)
                        d[jj] += __shfl_xor_sync(0xffffffffu, d[jj], off);
                }
                if (lane == 0) {
#pragma unroll
                    for (int jj = 0; jj < 4; jj++)
                        sm.s.wts[w * 32 + m + jj] = d[jj] * invsq;
                }
            }
        }
        __syncthreads();

        // ---- softmax over 256 exact logits ----
        float l = sm.s.wts[t];
        sm.s.red[t] = l; __syncthreads();
        for (int s = 128; s > 0; s >>= 1) { if (t < s) sm.s.red[t] = fmaxf(sm.s.red[t], sm.s.red[t + s]); __syncthreads(); }
        if (t == 0) s_m2 = sm.s.red[0];
        __syncthreads();
        float e = __expf(l - s_m2);
        sm.s.red[t] = e; __syncthreads();
        for (int s = 128; s > 0; s >>= 1) { if (t < s) sm.s.red[t] += sm.s.red[t + s]; __syncthreads(); }
        if (t == 0) s_Z2 = sm.s.red[0];
        __syncthreads();
        sm.s.wts[t] = e / s_Z2;
        __syncthreads();

        // ---- y = sum w_j V[idx_j]: warp-per-row gather, 4 in flight ----
        {
            const float4* Vr = (const float4*)(Vg + (size_t)h * SLEN * DIM);
            float4 acc = make_float4(0.f, 0.f, 0.f, 0.f);
#pragma unroll 1
            for (int m = 0; m < 32; m += 4) {
                float4 vv[4]; float wv[4];
#pragma unroll
                for (int jj = 0; jj < 4; jj++) {
                    int j = w * 32 + m + jj;
                    vv[jj] = Vr[(size_t)sm.s.idxs[j] * 32 + lane];
                    wv[jj] = sm.s.wts[j];
                }
#pragma unroll
                for (int jj = 0; jj < 4; jj++) {
                    acc.x += wv[jj] * vv[jj].x; acc.y += wv[jj] * vv[jj].y;
                    acc.z += wv[jj] * vv[jj].z; acc.w += wv[jj] * vv[jj].w;
                }
            }
            sm.s.yb[w][lane] = acc;
        }
        __syncthreads();
        if (t < 32) {
            float4 y = sm.s.yb[0][t];
#pragma unroll
            for (int i = 1; i < 8; i++) {
                float4 a = sm.s.yb[i][t];
                y.x += a.x; y.y += a.y; y.z += a.z; y.w += a.w;
            }
            ((float4*)(g_y + h * DIM))[t] = y;
        }
    } else {
        // ================== V-STREAM CTA ==================
        int v = bid - NH;
        h = v >> 3;
        int c = v & 7;
        int base = c * 512;
        const float4* Vr = (const float4*)(Vg + (size_t)h * SLEN * DIM);
        float4 am = make_float4(0.f, 0.f, 0.f, 0.f);
        for (int it = 0; it < 64; it += 8) {        // 8 rows in flight
            float4 vv[8];
#pragma unroll
            for (int j = 0; j < 8; j++)
                vv[j] = Vr[(size_t)(base + w + 8 * (it + j)) * 32 + lane];
#pragma unroll
            for (int j = 0; j < 8; j++) {
                am.x += vv[j].x; am.y += vv[j].y; am.z += vv[j].z; am.w += vv[j].w;
            }
        }
        sm.v.bm[w][lane] = am;
        __syncthreads();
        if (t < 32) {
            float4 s = sm.v.bm[0][t];
#pragma unroll
            for (int i = 1; i < 8; i++) {
                float4 a = sm.v.bm[i][t];
                s.x += a.x; s.y += a.y; s.z += a.z; s.w += a.w;
            }
            ((float4*)(g_vpart + (size_t)(h * 8 + c) * DIM))[t] = s;
        }
    }

    // ================== arrival + last-CTA combine ==================
    __threadfence();                        // publish this CTA's results
    __syncthreads();
    if (t == 0) s_rank = atomicAdd(&g_done[h], 1);
    __syncthreads();
    if (s_rank == 8) {                      // 9th (last) arrival combines
        __threadfence();                    // acquire peers' results
        if (t == 0) g_done[h] = 0;          // reset for next graph replay
        if (t < 32) {
            float4 vm = make_float4(0.f, 0.f, 0.f, 0.f);
#pragma unroll
            for (int cc = 0; cc < 8; cc++) {
                float4 p = ((const float4*)(g_vpart + (size_t)(h * 8 + cc) * DIM))[t];
                vm.x += p.x; vm.y += p.y; vm.z += p.z; vm.w += p.w;
            }
            const float inv = 1.f / (float)SLEN;
            vm.x *= inv; vm.y *= inv; vm.z *= inv; vm.w *= inv;
            float4 y = ((const float4*)(g_y + h * DIM))[t];
            float alpha = g_alpha[h];
            float4 o;
            o.x = vm.x + alpha * (y.x - vm.x);
            o.y = vm.y + alpha * (y.y - vm.y);
            o.z = vm.z + alpha * (y.z - vm.z);
            o.w = vm.w + alpha * (y.w - vm.w);
            ((float4*)out)[h * 32 + t] = o;
        }
    }
}

extern "C" void kernel_launch(void* const* d_in, const int* in_sizes, int n_in,
                              void* d_out, int out_size) {
    const float* Q = (const float*)d_in[0];
    const float* K = (const float*)d_in[1];
    const float* V = (const float*)d_in[2];
    // d_in[3] = mask (all true), d_in[4]=r, d_in[5]=k (compile-time constants)
    float* out = (float*)d_out;

    kpass_kernel<<<NH * 8, 256>>>(Q, K);
    fused_kernel<<<NH + NH * 8, 256>>>(Q, K, V, out);
}